// round 1
// baseline (speedup 1.0000x reference)
#include <cuda_runtime.h>
#include <cstddef>

// Persistent-kernel LSTM:  B=512, S=512, D=128, H=256, 4H=1024.
// One kernel launch; 512 time steps separated by a device-wide ticket barrier.
// Per step: fused GEMM  z[512,1024] = [x_t | h] ([512,384]) @ [Wx;Wh] ([384,1024])
// computed with packed fp32x2 FMAs, then gate nonlinearities with c kept in
// registers, h double-buffered in global scratch. Final: h@Wd + softmax.

#define SEQ    512
#define BATCH  512
#define DIM    128
#define HID    256
#define G4     1024
#define NCTA   128
#define NTHR   128
#define KTOT   384
#define KC     16
#define NCHUNK 24        // 384 / 16
#define PITCH  68        // smem row pitch (floats), multiple of 4, breaks conflicts

// ---- persistent device scratch (no allocations allowed) ----
__device__ float g_h[2][BATCH * HID];          // double-buffered hidden state
__device__ unsigned long long g_bar = 0;       // monotonic barrier ticket

// ---- packed fp32x2 helpers ----
__device__ __forceinline__ void fma2(unsigned long long &d,
                                     unsigned long long a,
                                     unsigned long long b) {
    asm("fma.rn.f32x2 %0, %1, %2, %0;" : "+l"(d) : "l"(a), "l"(b));
}
__device__ __forceinline__ unsigned long long pack2(float x) {
    unsigned long long r;
    asm("mov.b64 %0, {%1, %1};" : "=l"(r) : "f"(x));
    return r;
}
__device__ __forceinline__ float2 unpack2(unsigned long long v) {
    float2 f;
    asm("mov.b64 {%0, %1}, %2;" : "=f"(f.x), "=f"(f.y) : "l"(v));
    return f;
}

__device__ __forceinline__ float sigf(float x) {
    return __fdividef(1.0f, 1.0f + __expf(-x));
}
__device__ __forceinline__ float tanhf_fast(float x) {
    // 1 - 2/(1+e^{2x}); saturates correctly at +-1 for large |x|
    return 1.0f - __fdividef(2.0f, 1.0f + __expf(2.0f * x));
}

// Monotonic ticket grid barrier: correct across any number of graph replays.
__device__ __forceinline__ void grid_barrier() {
    __syncthreads();
    if (threadIdx.x == 0) {
        __threadfence();                                  // release h writes
        unsigned long long t = atomicAdd(&g_bar, 1ULL) + 1ULL;
        unsigned long long target =
            ((t + (unsigned long long)NCTA - 1ULL) / NCTA) * (unsigned long long)NCTA;
        unsigned long long v;
        do {
            asm volatile("ld.acquire.gpu.u64 %0, [%1];"
                         : "=l"(v) : "l"(&g_bar) : "memory");
        } while (v < target);
    }
    __syncthreads();
}

__global__ void __launch_bounds__(NTHR, 1)
lstm_persistent(const float* __restrict__ x,  const float* __restrict__ Wx,
                const float* __restrict__ Wh, const float* __restrict__ bv,
                const float* __restrict__ Wd, const float* __restrict__ bd,
                float* __restrict__ out)
{
    __shared__ __align__(16) float As[2][KC * PITCH];   // A tile, transposed [k][row]
    __shared__ __align__(16) float Bs[2][KC * PITCH];   // W tile [k][64 gate-cols]

    const int tid = threadIdx.x;
    const int cta = blockIdx.x;
    const int rt  = cta >> 4;          // 0..7  row tile (64 rows)
    const int jt  = cta & 15;          // 0..15 j tile (16 hidden cols x 4 gates)
    const int r0  = rt * 64;
    const int j0  = jt * 16;
    const int jj  = tid & 15;          // hidden-col within tile
    const int rg  = tid >> 4;          // row group 0..7 (8 rows each)
    const int myrow0 = r0 + rg * 8;

    // zero h buffer 0 (h0 = 0); every launch, deterministic
    {
        int base = cta * NTHR + tid;
        #pragma unroll
        for (int i = 0; i < 8; ++i)
            g_h[0][base + i * (NCTA * NTHR)] = 0.0f;
    }

    const float bias0 = bv[0 * 256 + j0 + jj];
    const float bias1 = bv[1 * 256 + j0 + jj];
    const float bias2 = bv[2 * 256 + j0 + jj];
    const float bias3 = bv[3 * 256 + j0 + jj];

    float2 c2[4];                       // cell state: 8 rows x 1 jj, row-paired
    #pragma unroll
    for (int p = 0; p < 4; ++p) c2[p] = make_float2(0.f, 0.f);

    // loader coordinates (each thread loads 2 float4 of A and 2 float4 of B per chunk)
    const int aIdx0 = tid, aIdx1 = tid + NTHR;
    const int arow0 = aIdx0 >> 2, ak0 = (aIdx0 & 3) << 2;
    const int arow1 = aIdx1 >> 2, ak1 = (aIdx1 & 3) << 2;
    const int bk0 = aIdx0 >> 4, bc0 = aIdx0 & 15;
    const int bk1 = aIdx1 >> 4, bc1 = aIdx1 & 15;
    const int bcol0 = (bc0 >> 2) * 256 + j0 + ((bc0 & 3) << 2);
    const int bcol1 = (bc1 >> 2) * 256 + j0 + ((bc1 & 3) << 2);

    grid_barrier();                     // h0 zeroing visible everywhere

    for (int s = 0; s < SEQ; ++s) {
        const float* __restrict__ hprev = g_h[s & 1];
        float* __restrict__ hnext = g_h[(s + 1) & 1];

        unsigned long long acc[4][4];   // [gate][row-pair], packed fp32x2
        #pragma unroll
        for (int q = 0; q < 4; ++q)
            #pragma unroll
            for (int p = 0; p < 4; ++p) acc[q][p] = 0ULL;

        float4 aR0, aR1, bR0, bR1;

        auto ldg_chunk = [&](int kbase) {
            if (kbase < DIM) {          // x part of K
                aR0 = *(const float4*)(x + ((size_t)(r0 + arow0) * SEQ + s) * DIM + kbase + ak0);
                aR1 = *(const float4*)(x + ((size_t)(r0 + arow1) * SEQ + s) * DIM + kbase + ak1);
                bR0 = *(const float4*)(Wx + (size_t)(kbase + bk0) * G4 + bcol0);
                bR1 = *(const float4*)(Wx + (size_t)(kbase + bk1) * G4 + bcol1);
            } else {                    // h part of K: MUST bypass L1 (cross-SM coherence)
                int kb = kbase - DIM;
                aR0 = __ldcv((const float4*)(hprev + (size_t)(r0 + arow0) * HID + kb + ak0));
                aR1 = __ldcv((const float4*)(hprev + (size_t)(r0 + arow1) * HID + kb + ak1));
                bR0 = *(const float4*)(Wh + (size_t)(kb + bk0) * G4 + bcol0);
                bR1 = *(const float4*)(Wh + (size_t)(kb + bk1) * G4 + bcol1);
            }
        };
        auto sts_chunk = [&](int buf) {
            float* A = As[buf];
            float* B = Bs[buf];
            A[(ak0 + 0) * PITCH + arow0] = aR0.x;
            A[(ak0 + 1) * PITCH + arow0] = aR0.y;
            A[(ak0 + 2) * PITCH + arow0] = aR0.z;
            A[(ak0 + 3) * PITCH + arow0] = aR0.w;
            A[(ak1 + 0) * PITCH + arow1] = aR1.x;
            A[(ak1 + 1) * PITCH + arow1] = aR1.y;
            A[(ak1 + 2) * PITCH + arow1] = aR1.z;
            A[(ak1 + 3) * PITCH + arow1] = aR1.w;
            *(float4*)(B + bk0 * PITCH + bc0 * 4) = bR0;
            *(float4*)(B + bk1 * PITCH + bc1 * 4) = bR1;
        };

        ldg_chunk(0);
        sts_chunk(0);
        __syncthreads();

        #pragma unroll 2
        for (int ch = 0; ch < NCHUNK; ++ch) {
            if (ch + 1 < NCHUNK) ldg_chunk((ch + 1) * KC);
            const float* Ab = As[ch & 1];
            const float* Bb = Bs[ch & 1];
            #pragma unroll
            for (int kk = 0; kk < KC; ++kk) {
                ulonglong2 a01 = *(const ulonglong2*)(Ab + kk * PITCH + rg * 8);
                ulonglong2 a23 = *(const ulonglong2*)(Ab + kk * PITCH + rg * 8 + 4);
                #pragma unroll
                for (int q = 0; q < 4; ++q) {
                    unsigned long long bw = pack2(Bb[kk * PITCH + q * 16 + jj]);
                    fma2(acc[q][0], a01.x, bw);
                    fma2(acc[q][1], a01.y, bw);
                    fma2(acc[q][2], a23.x, bw);
                    fma2(acc[q][3], a23.y, bw);
                }
            }
            if (ch + 1 < NCHUNK) sts_chunk((ch + 1) & 1);
            __syncthreads();
        }

        // gate epilogue: i,f,g,o -> c,h   (keras order i,f,c,o)
        #pragma unroll
        for (int p = 0; p < 4; ++p) {
            float2 vi = unpack2(acc[0][p]);
            float2 vf = unpack2(acc[1][p]);
            float2 vg = unpack2(acc[2][p]);
            float2 vo = unpack2(acc[3][p]);
            float i0 = sigf(vi.x + bias0),       i1 = sigf(vi.y + bias0);
            float f0 = sigf(vf.x + bias1),       f1 = sigf(vf.y + bias1);
            float gg0 = tanhf_fast(vg.x + bias2), gg1 = tanhf_fast(vg.y + bias2);
            float o0 = sigf(vo.x + bias3),       o1 = sigf(vo.y + bias3);
            c2[p].x = f0 * c2[p].x + i0 * gg0;
            c2[p].y = f1 * c2[p].y + i1 * gg1;
            hnext[(size_t)(myrow0 + 2 * p)     * HID + j0 + jj] = o0 * tanhf_fast(c2[p].x);
            hnext[(size_t)(myrow0 + 2 * p + 1) * HID + j0 + jj] = o1 * tanhf_fast(c2[p].y);
        }

        grid_barrier();
    }

    // ---- classifier + softmax on h_final = g_h[0]; one warp per batch row ----
    {
        const int w = tid >> 5, lane = tid & 31;
        const int row = cta * 4 + w;                  // 128 CTAs x 4 warps = 512 rows
        const float* hf = g_h[0];
        float acc10[10];
        #pragma unroll
        for (int c = 0; c < 10; ++c) acc10[c] = 0.f;
        for (int k = lane; k < HID; k += 32) {
            float hv = __ldcv(hf + (size_t)row * HID + k);
            const float* wd = Wd + (size_t)k * 10;
            #pragma unroll
            for (int c = 0; c < 10; ++c) acc10[c] += hv * wd[c];
        }
        #pragma unroll
        for (int off = 16; off > 0; off >>= 1) {
            #pragma unroll
            for (int c = 0; c < 10; ++c)
                acc10[c] += __shfl_down_sync(0xffffffffu, acc10[c], off);
        }
        if (lane == 0) {
            float m = -3.0e38f;
            #pragma unroll
            for (int c = 0; c < 10; ++c) { acc10[c] += bd[c]; m = fmaxf(m, acc10[c]); }
            float ssum = 0.f;
            #pragma unroll
            for (int c = 0; c < 10; ++c) { acc10[c] = __expf(acc10[c] - m); ssum += acc10[c]; }
            float inv = 1.0f / ssum;
            #pragma unroll
            for (int c = 0; c < 10; ++c)
                out[(size_t)row * 10 + c] = acc10[c] * inv;
        }
    }
}

extern "C" void kernel_launch(void* const* d_in, const int* in_sizes, int n_in,
                              void* d_out, int out_size) {
    const float* x  = (const float*)d_in[0];
    const float* Wx = (const float*)d_in[1];
    const float* Wh = (const float*)d_in[2];
    const float* b  = (const float*)d_in[3];
    const float* Wd = (const float*)d_in[4];
    const float* bd = (const float*)d_in[5];
    (void)in_sizes; (void)n_in; (void)out_size;
    lstm_persistent<<<NCTA, NTHR>>>(x, Wx, Wh, b, Wd, bd, (float*)d_out);
}

// round 2
// speedup vs baseline: 1.4830x; 1.4830x over previous
#include <cuda_runtime.h>
#include <cstddef>

// Persistent-kernel LSTM:  B=512, S=512, D=128, H=256, 4H=1024.
// R2: 256 threads/CTA (2 warps per SMSP for latency hiding), weights resident
// in shared memory for the whole sequence, gate-packed B layout so the inner
// loop is 2xLDS.128 + 4xMOV + 8xFFMA2 per k per thread.

#define SEQ    512
#define BATCH  512
#define DIM    128
#define HID    256
#define G4     1024
#define NCTA   128
#define NTHR   256
#define KTOT   384
#define KC     32
#define NCHUNK 12            // 384 / 32
#define PITCH  68            // A-tile row pitch (floats), 16B-aligned rows
#define SB_FLOATS (KTOT * 64)          // persistent weight slice: 96 KB
#define SA_FLOATS (KC * PITCH)         // one A buffer: 8.5 KB
#define SMEM_BYTES ((SB_FLOATS + 2 * SA_FLOATS) * 4)

// ---- persistent device scratch (no allocations allowed) ----
__device__ float g_h[2][BATCH * HID];          // double-buffered hidden state
__device__ unsigned long long g_bar = 0;       // monotonic barrier ticket

// ---- packed fp32x2 helpers ----
__device__ __forceinline__ void fma2(unsigned long long &d,
                                     unsigned long long a,
                                     unsigned long long b) {
    asm("fma.rn.f32x2 %0, %1, %2, %0;" : "+l"(d) : "l"(a), "l"(b));
}
__device__ __forceinline__ unsigned long long pack2(float x) {
    unsigned long long r;
    asm("mov.b64 %0, {%1, %1};" : "=l"(r) : "f"(x));
    return r;
}
__device__ __forceinline__ float2 unpack2(unsigned long long v) {
    float2 f;
    asm("mov.b64 {%0, %1}, %2;" : "=f"(f.x), "=f"(f.y) : "l"(v));
    return f;
}

__device__ __forceinline__ float sigf(float x) {
    return __fdividef(1.0f, 1.0f + __expf(-x));
}
__device__ __forceinline__ float tanhf_fast(float x) {
    return 1.0f - __fdividef(2.0f, 1.0f + __expf(2.0f * x));
}

// Monotonic ticket grid barrier: correct across any number of graph replays.
__device__ __forceinline__ void grid_barrier() {
    __syncthreads();
    if (threadIdx.x == 0) {
        __threadfence();                                  // release h writes
        unsigned long long t = atomicAdd(&g_bar, 1ULL) + 1ULL;
        unsigned long long target =
            ((t + (unsigned long long)NCTA - 1ULL) / NCTA) * (unsigned long long)NCTA;
        unsigned long long v;
        do {
            asm volatile("ld.acquire.gpu.u64 %0, [%1];"
                         : "=l"(v) : "l"(&g_bar) : "memory");
        } while (v < target);
    }
    __syncthreads();
}

__global__ void __launch_bounds__(NTHR, 1)
lstm_persistent(const float* __restrict__ x,  const float* __restrict__ Wx,
                const float* __restrict__ Wh, const float* __restrict__ bv,
                const float* __restrict__ Wd, const float* __restrict__ bd,
                float* __restrict__ out)
{
    extern __shared__ __align__(16) float smem[];
    float* sB = smem;                    // [k][jj*4 + gate], 384 x 64
    float* sA = smem + SB_FLOATS;        // 2 buffers of [k][row] (KC x PITCH)

    const int tid = threadIdx.x;
    const int cta = blockIdx.x;
    const int rt  = cta >> 4;            // 0..7   row tile (64 rows)
    const int jt  = cta & 15;            // 0..15  col tile (16 hidden cols)
    const int r0  = rt * 64;
    const int j0  = jt * 16;
    const int jj  = tid & 15;            // hidden-col within tile
    const int rq  = tid >> 4;            // 0..15, 4 rows each
    const int myr0 = r0 + rq * 4;

    // ---- one-time: load this CTA's 64-column weight slice into smem ----
    // layout: sB[k*64 + jj*4 + gate], gates (i,f,g,o) adjacent per column.
    for (int idx = tid; idx < SB_FLOATS; idx += NTHR) {
        int k = idx >> 6, col = idx & 63;
        int g = col & 3, jjl = col >> 2;
        int gcol = g * HID + j0 + jjl;
        sB[idx] = (k < DIM) ? Wx[(size_t)k * G4 + gcol]
                            : Wh[(size_t)(k - DIM) * G4 + gcol];
    }

    // zero h buffer 0 (h0 = 0); every launch, deterministic
    {
        int base = cta * NTHR + tid;
        #pragma unroll
        for (int i = 0; i < 4; ++i)
            g_h[0][base + i * (NCTA * NTHR)] = 0.0f;
    }

    const float bi = bv[0 * HID + j0 + jj];
    const float bf = bv[1 * HID + j0 + jj];
    const float bg = bv[2 * HID + j0 + jj];
    const float bo = bv[3 * HID + j0 + jj];

    float c4[4] = {0.f, 0.f, 0.f, 0.f};  // cell state: 4 rows x 1 col

    // A loader: each thread brings 2 float4 per chunk (rows lrow0 / lrow0+32)
    const int lrow0 = tid >> 3;          // 0..31
    const int lk0   = (tid & 7) << 2;    // 0,4,...,28

    grid_barrier();                       // h0 + sB visible everywhere

    for (int s = 0; s < SEQ; ++s) {
        const float* __restrict__ hprev = g_h[s & 1];
        float* __restrict__ hnext = g_h[(s + 1) & 1];

        unsigned long long acc[4][2];     // [row][gatepair (i,f)/(g,o)]
        #pragma unroll
        for (int r = 0; r < 4; ++r) { acc[r][0] = 0ULL; acc[r][1] = 0ULL; }

        float4 aR0, aR1;
        auto ldg_chunk = [&](int kbase) {
            if (kbase < DIM) {            // x part of K
                const float* p = x + ((size_t)(r0 + lrow0) * SEQ + s) * DIM + kbase + lk0;
                aR0 = *(const float4*)p;
                aR1 = *(const float4*)(p + (size_t)32 * SEQ * DIM);
            } else {                      // h part: bypass L1 (cross-SM coherence)
                int kb = kbase - DIM;
                const float4* p = (const float4*)(hprev + (size_t)(r0 + lrow0) * HID + kb + lk0);
                aR0 = __ldcv(p);
                aR1 = __ldcv((const float4*)((const float*)p + 32 * HID));
            }
        };
        auto sts_chunk = [&](int buf) {
            float* A = sA + buf * SA_FLOATS;
            A[(lk0 + 0) * PITCH + lrow0] = aR0.x;
            A[(lk0 + 1) * PITCH + lrow0] = aR0.y;
            A[(lk0 + 2) * PITCH + lrow0] = aR0.z;
            A[(lk0 + 3) * PITCH + lrow0] = aR0.w;
            A[(lk0 + 0) * PITCH + lrow0 + 32] = aR1.x;
            A[(lk0 + 1) * PITCH + lrow0 + 32] = aR1.y;
            A[(lk0 + 2) * PITCH + lrow0 + 32] = aR1.z;
            A[(lk0 + 3) * PITCH + lrow0 + 32] = aR1.w;
        };

        ldg_chunk(0);
        sts_chunk(0);
        __syncthreads();

        #pragma unroll 1
        for (int ch = 0; ch < NCHUNK; ++ch) {
            if (ch + 1 < NCHUNK) ldg_chunk((ch + 1) * KC);
            const float* Ab = sA + (ch & 1) * SA_FLOATS;
            const float* Bb = sB + ch * (KC * 64);
            #pragma unroll
            for (int kk = 0; kk < KC; ++kk) {
                float4 av = *(const float4*)(Ab + kk * PITCH + rq * 4);
                ulonglong2 bw = *(const ulonglong2*)(Bb + kk * 64 + jj * 4);
                unsigned long long a0 = pack2(av.x), a1 = pack2(av.y);
                unsigned long long a2 = pack2(av.z), a3 = pack2(av.w);
                fma2(acc[0][0], a0, bw.x); fma2(acc[0][1], a0, bw.y);
                fma2(acc[1][0], a1, bw.x); fma2(acc[1][1], a1, bw.y);
                fma2(acc[2][0], a2, bw.x); fma2(acc[2][1], a2, bw.y);
                fma2(acc[3][0], a3, bw.x); fma2(acc[3][1], a3, bw.y);
            }
            if (ch + 1 < NCHUNK) sts_chunk((ch + 1) & 1);
            __syncthreads();
        }

        // gate epilogue (keras order i,f,g,o): c,h update, h -> global
        #pragma unroll
        for (int r = 0; r < 4; ++r) {
            float2 vif = unpack2(acc[r][0]);
            float2 vgo = unpack2(acc[r][1]);
            float iv = sigf(vif.x + bi);
            float fv = sigf(vif.y + bf);
            float gv = tanhf_fast(vgo.x + bg);
            float ov = sigf(vgo.y + bo);
            c4[r] = fv * c4[r] + iv * gv;
            hnext[(size_t)(myr0 + r) * HID + j0 + jj] = ov * tanhf_fast(c4[r]);
        }

        grid_barrier();
    }

    // ---- classifier + softmax on h_final = g_h[0]; one warp per batch row ----
    {
        const int w = tid >> 5, lane = tid & 31;
        if (w < 4) {
            const int row = cta * 4 + w;              // 128 CTAs x 4 warps = 512 rows
            const float* hf = g_h[0];
            float acc10[10];
            #pragma unroll
            for (int c = 0; c < 10; ++c) acc10[c] = 0.f;
            for (int k = lane; k < HID; k += 32) {
                float hv = __ldcv(hf + (size_t)row * HID + k);
                const float* wd = Wd + (size_t)k * 10;
                #pragma unroll
                for (int c = 0; c < 10; ++c) acc10[c] += hv * wd[c];
            }
            #pragma unroll
            for (int off = 16; off > 0; off >>= 1) {
                #pragma unroll
                for (int c = 0; c < 10; ++c)
                    acc10[c] += __shfl_down_sync(0xffffffffu, acc10[c], off);
            }
            if (lane == 0) {
                float m = -3.0e38f;
                #pragma unroll
                for (int c = 0; c < 10; ++c) { acc10[c] += bd[c]; m = fmaxf(m, acc10[c]); }
                float ssum = 0.f;
                #pragma unroll
                for (int c = 0; c < 10; ++c) { acc10[c] = __expf(acc10[c] - m); ssum += acc10[c]; }
                float inv = 1.0f / ssum;
                #pragma unroll
                for (int c = 0; c < 10; ++c)
                    out[(size_t)row * 10 + c] = acc10[c] * inv;
            }
        }
    }
}

extern "C" void kernel_launch(void* const* d_in, const int* in_sizes, int n_in,
                              void* d_out, int out_size) {
    const float* x  = (const float*)d_in[0];
    const float* Wx = (const float*)d_in[1];
    const float* Wh = (const float*)d_in[2];
    const float* b  = (const float*)d_in[3];
    const float* Wd = (const float*)d_in[4];
    const float* bd = (const float*)d_in[5];
    (void)in_sizes; (void)n_in; (void)out_size;
    cudaFuncSetAttribute(lstm_persistent,
                         cudaFuncAttributeMaxDynamicSharedMemorySize, SMEM_BYTES);
    lstm_persistent<<<NCTA, NTHR, SMEM_BYTES>>>(x, Wx, Wh, b, Wd, bd, (float*)d_out);
}